// round 12
// baseline (speedup 1.0000x reference)
#include <cuda_runtime.h>
#include <math.h>
#include <stdint.h>

// VIN full-grid 8-CTA cluster (R5 design, 23.0us) + R11's weight-residency
// fix: 4 lanes per cell-pair, 2 actions per lane -> 18 packed weight u64
// (36 regs) per thread, register-resident. 512 threads, 2 tasks/thread over
// the CTA's 8-row band; per-iteration halo exchange via st.shared::cluster +
// remote mbarrier.arrive.release; triple-buffered v makes skew-1 safe.
// Halos are pushed on the LAST sweep too (+ closing cluster_sync) so
// band-edge queries read exact v19. Only batch 0 reaches the output; the
// 150-ch hidden conv collapses into a 2-ch 3x3 effective conv; the r-part
// of q (qr) is precomputed once.

#define NCL 8                  // cluster CTAs
#define RPC 8                  // own rows per CTA
#define PW 66                  // padded row stride
#define LROWS 10               // band rows + 2 halo
#define XROWS 12               // X band rows needed for r over LROWS
#define NTH 512
#define NSWEEP 19              // final q uses v after 19 updates
#define NACT 8
#define QSTR 516               // u64 per sub plane: 8*32*2 + 4 (bank pad)

__device__ __forceinline__ uint32_t s2u(const void* p) {
    return (uint32_t)__cvta_generic_to_shared(p);
}
__device__ __forceinline__ uint64_t pack2(float x, float y) {
    uint64_t r;
    asm("mov.b64 %0, {%1, %2};" : "=l"(r) : "f"(x), "f"(y));
    return r;
}
__device__ __forceinline__ float2 unpack2(uint64_t v) {
    float2 f;
    asm("mov.b64 {%0, %1}, %2;" : "=f"(f.x), "=f"(f.y) : "l"(v));
    return f;
}
__device__ __forceinline__ uint64_t fma2(uint64_t a, uint64_t b, uint64_t c) {
    uint64_t d;
    asm("fma.rn.f32x2 %0, %1, %2, %3;" : "=l"(d) : "l"(a), "l"(b), "l"(c));
    return d;
}
__device__ __forceinline__ void cluster_sync() {
    asm volatile("barrier.cluster.arrive.aligned;" ::: "memory");
    asm volatile("barrier.cluster.wait.aligned;" ::: "memory");
}
// one f32 into a neighbor CTA's smem, then release-arrive its mbarrier
__device__ __forceinline__ void halo_out1(uint32_t laddr, uint32_t rank,
                                          float v, uint32_t lmbar) {
    asm volatile(
        "{\n\t.reg .b32 ra, rb;\n\t"
        "mapa.shared::cluster.u32 ra, %0, %1;\n\t"
        "st.shared::cluster.f32 [ra], %2;\n\t"
        "mapa.shared::cluster.u32 rb, %3, %1;\n\t"
        "mbarrier.arrive.release.cluster.shared::cluster.b64 _, [rb];\n\t}"
        :: "r"(laddr), "r"(rank), "f"(v), "r"(lmbar) : "memory");
}
__device__ __forceinline__ void mbar_wait(uint32_t addr, uint32_t parity) {
    asm volatile(
        "{\n\t.reg .pred P;\n\t"
        "W%=:\n\t"
        "mbarrier.try_wait.parity.acquire.cluster.shared::cta.b64 P, [%0], %1, 0x989680;\n\t"
        "@P bra D%=;\n\t"
        "bra W%=;\n\t"
        "D%=:\n\t}"
        :: "r"(addr), "r"(parity) : "memory");
}

// One sweep pass for task (ROFF/QOFF/SOFF precomputed). Writes v0/v1 via
// lanes sub0/sub1; optional remote push (PUSH) to neighbor NRANK at ROFFR.
#define PASS(QOFF, ROFF, SOFF, PUSH, NRANK, ROFFR)                            \
{                                                                             \
    ulonglong2 qq = *(const ulonglong2*)(qr2s + (QOFF));                      \
    uint64_t a0 = qq.x, a1 = qq.y;                                            \
    _Pragma("unroll")                                                         \
    for (int ky = 0; ky < 3; ky++) {                                          \
        const uint64_t* rowp = (const uint64_t*)(cur + (ROFF) + ky * PW);     \
        uint64_t a01 = rowp[0], a23 = rowp[1];                                \
        float2 f01 = unpack2(a01), f23 = unpack2(a23);                        \
        uint64_t pm = pack2(f01.y, f23.x);                                    \
        a0 = fma2(wpA[ky * 3 + 0], a01, a0);                                  \
        a0 = fma2(wpA[ky * 3 + 1], pm,  a0);                                  \
        a0 = fma2(wpA[ky * 3 + 2], a23, a0);                                  \
        a1 = fma2(wpB[ky * 3 + 0], a01, a1);                                  \
        a1 = fma2(wpB[ky * 3 + 1], pm,  a1);                                  \
        a1 = fma2(wpB[ky * 3 + 2], a23, a1);                                  \
    }                                                                         \
    float2 f0 = unpack2(a0), f1 = unpack2(a1);                                \
    float v0 = fmaxf(f0.x, f1.x);                                             \
    float v1 = fmaxf(f0.y, f1.y);                                             \
    v0 = fmaxf(v0, __shfl_xor_sync(0xffffffffu, v0, 1));                      \
    v1 = fmaxf(v1, __shfl_xor_sync(0xffffffffu, v1, 1));                      \
    v0 = fmaxf(v0, __shfl_xor_sync(0xffffffffu, v0, 2));                      \
    v1 = fmaxf(v1, __shfl_xor_sync(0xffffffffu, v1, 2));                      \
    if (sub < 2) {                                                            \
        float vs = (sub & 1) ? v1 : v0;                                       \
        nxt[SOFF] = vs;                                                       \
        if (PUSH) halo_out1(s2u(nxt + (ROFFR)), (NRANK), vs, mb);             \
    }                                                                         \
}

__global__ __launch_bounds__(NTH, 1) __cluster_dims__(NCL, 1, 1)
void vin_kernel(const float* __restrict__ X,
                const int* __restrict__ S1,
                const int* __restrict__ S2,
                const float* __restrict__ Wh,
                const float* __restrict__ bh,
                const float* __restrict__ Wr,
                const float* __restrict__ Wq,
                float* __restrict__ out)
{
    __shared__ __align__(16) unsigned long long qr2[4 * QSTR];  // [sub][row][pair][2]
    __shared__ float Xs[2 * XROWS * PW];   // X band, zero-padded
    __shared__ float rp[LROWS * PW];       // reward band (rows rbase-1..rbase+8)
    __shared__ float vbuf[3][LROWS * PW];  // v triple buffer
    __shared__ float wqs[144];
    __shared__ float part[19 * 8];
    __shared__ float weff[19];
    __shared__ unsigned long long mbar;

    const int t = threadIdx.x;
    const int rank = blockIdx.x;
    const int rbase = rank * RPC;
    const int sub = t & 3;                 // lane-in-task: actions 2sub, 2sub+1
    const uint64_t* qr2s = (const uint64_t*)qr2 + sub * QSTR;
    const uint32_t mb = s2u(&mbar);

    // task geometry (2 tasks per thread)
    const int row0 = t >> 7;               // k0: band rows 0..3
    const int row1 = row0 + 4;             // k1: band rows 4..7
    const int p = (t >> 2) & 31;           // pair: cells at global cols 2p, 2p+1
    const int c0 = 1 + 2 * p;              // padded col of cell .x
    const int roffA = row0 * PW + 2 * p;   // v/r read base (buffer rows row..row+2)
    const int roffB = row1 * PW + 2 * p;
    const unsigned qoffA = (unsigned)((row0 * 32 + p) * 2);
    const unsigned qoffB = (unsigned)((row1 * 32 + p) * 2);
    const int soffA = (row0 + 1) * PW + c0 + (sub & 1);
    const int soffB = (row1 + 1) * PW + c0 + (sub & 1);
    const bool isTop = (row0 == 0) && (rank > 0);           // push band row 0 up
    const bool isBot = (row1 == 7) && (rank < NCL - 1);     // push band row 7 down
    const bool waiter = isTop || isBot;
    const int roffRT = 9 * PW + c0 + (sub & 1);  // remote: upper nbr's bottom halo
    const int roffRB = c0 + (sub & 1);           // remote: lower nbr's top halo

    // ---- init: zero buffers (halos/padding stay 0), stage weights, mbar ----
    for (int i = t; i < LROWS * PW; i += NTH) {
        vbuf[0][i] = 0.f; vbuf[1][i] = 0.f; vbuf[2][i] = 0.f; rp[i] = 0.f;
    }
    if (t < 144) wqs[t] = Wq[t];
    if (t < 152) {
        int pp = t >> 3, c = t & 7;
        float s = 0.f;
        for (int h = c; h < 150; h += 8)
            s += Wr[h] * (pp < 18 ? Wh[h * 18 + pp] : bh[h]);
        part[pp * 8 + c] = s;
    }
    if (t == 0) {
        int nb = (rank > 0) + (rank < NCL - 1);
        asm volatile("mbarrier.init.shared.b64 [%0], %1;"
                     :: "r"(mb), "r"(64 * nb) : "memory");
    }
    __syncthreads();
    if (t < 19) {
        float s = 0.f;
        #pragma unroll
        for (int c = 0; c < 8; c++) s += part[t * 8 + c];
        weff[t] = s;
    }
    // ---- load X band (rows rbase-2..rbase+9), zero outside grid ----
    for (int idx = t; idx < 2 * XROWS * PW; idx += NTH) {
        int c = idx / (XROWS * PW);
        int rem = idx - c * (XROWS * PW);
        int br = rem / PW;
        int bx = rem - br * PW;
        int gy = rbase - 2 + br, gx = bx - 1;
        float v = 0.f;
        if (gy >= 0 && gy < 64 && gx >= 0 && gx < 64)
            v = X[c * 4096 + gy * 64 + gx];
        Xs[c * XROWS * PW + br * PW + bx] = v;
    }
    __syncthreads();

    // ---- reward r over rows rbase-1..rbase+8 (in-grid only; else stays 0) ----
    {
        float we[18];
        #pragma unroll
        for (int q = 0; q < 18; q++) we[q] = weff[q];
        const float b0 = weff[18];
        for (int idx = t; idx < LROWS * 64; idx += NTH) {
            int br = idx >> 6, j = idx & 63;
            int gy = rbase - 1 + br;
            if (gy < 0 || gy >= 64) continue;
            float acc = b0;
            #pragma unroll
            for (int c = 0; c < 2; c++)
                #pragma unroll
                for (int ky = 0; ky < 3; ky++)
                    #pragma unroll
                    for (int kx = 0; kx < 3; kx++)
                        acc = fmaf(we[c * 9 + ky * 3 + kx],
                                   Xs[c * XROWS * PW + (br + ky) * PW + j + kx],
                                   acc);
            rp[br * PW + j + 1] = acc;
        }
    }
    __syncthreads();

    // ---- qr = conv(r, Wq[:,0]) for own 8x64 band cells, once ----
    {
        uint64_t wrA[9], wrB[9];
        #pragma unroll
        for (int q = 0; q < 9; q++) {
            float wa = wqs[(2 * sub) * 18 + q];
            float wb = wqs[(2 * sub + 1) * 18 + q];
            wrA[q] = pack2(wa, wa);
            wrB[q] = pack2(wb, wb);
        }
        #pragma unroll
        for (int k = 0; k < 2; k++) {
            const int roff = k ? roffB : roffA;
            const unsigned qoff = k ? qoffB : qoffA;
            uint64_t a0 = 0ull, a1 = 0ull;
            #pragma unroll
            for (int ky = 0; ky < 3; ky++) {
                const uint64_t* rowp = (const uint64_t*)(rp + roff + ky * PW);
                uint64_t a01 = rowp[0], a23 = rowp[1];
                float2 f01 = unpack2(a01), f23 = unpack2(a23);
                uint64_t pm = pack2(f01.y, f23.x);
                a0 = fma2(wrA[ky * 3 + 0], a01, a0);
                a0 = fma2(wrA[ky * 3 + 1], pm,  a0);
                a0 = fma2(wrA[ky * 3 + 2], a23, a0);
                a1 = fma2(wrB[ky * 3 + 0], a01, a1);
                a1 = fma2(wrB[ky * 3 + 1], pm,  a1);
                a1 = fma2(wrB[ky * 3 + 2], a23, a1);
            }
            ulonglong2 qq; qq.x = a0; qq.y = a1;
            *(ulonglong2*)((uint64_t*)qr2 + sub * QSTR + qoff) = qq;
        }
    }

    // v-channel weights (18 u64 = 36 regs, register-resident)
    uint64_t wpA[9], wpB[9];
    #pragma unroll
    for (int q = 0; q < 9; q++) {
        float wa = wqs[(2 * sub) * 18 + 9 + q];
        float wb = wqs[(2 * sub + 1) * 18 + 9 + q];
        wpA[q] = pack2(wa, wa);
        wpB[q] = pack2(wb, wb);
    }
    __syncthreads();
    cluster_sync();   // mbar init + zeroed buffers visible cluster-wide

    // ---- 19 VI sweeps (it=0 reads zeroed cur => v1 = max_a qr) ----
    float* cur = vbuf[0];
    float* nxt = vbuf[1];
    float* oth = vbuf[2];
    for (int it = 0; it < NSWEEP; it++) {
        if (it > 0 && waiter) mbar_wait(mb, (it - 1) & 1);
        PASS(qoffA, roffA, soffA, isTop, (uint32_t)(rank - 1), roffRT);
        PASS(qoffB, roffB, soffB, isBot, (uint32_t)(rank + 1), roffRB);
        __syncthreads();
        float* tmp = cur; cur = nxt; nxt = oth; oth = tmp;
    }
    cluster_sync();   // final halo pushes visible; no CTA exits early

    // ---- q at the 64 query points from v19 (exact halos), softmax ----
    if (t < 64) {
        int qi = S1[t], qj = S2[t];
        if (qi >= rbase && qi < rbase + RPC) {
            int lr = qi - rbase;                  // band row; buffer rows lr..lr+2
            float q[NACT];
            float m = -INFINITY;
            #pragma unroll
            for (int a = 0; a < NACT; a++) {
                uint64_t qv = qr2[(a >> 1) * QSTR + (lr * 32 + (qj >> 1)) * 2 + (a & 1)];
                float2 f = unpack2(qv);
                float acc = (qj & 1) ? f.y : f.x;
                #pragma unroll
                for (int ky = 0; ky < 3; ky++)
                    #pragma unroll
                    for (int kx = 0; kx < 3; kx++)
                        acc = fmaf(wqs[a * 18 + 9 + ky * 3 + kx],
                                   cur[(lr + ky) * PW + qj + kx], acc);
                q[a] = acc;
                m = fmaxf(m, acc);
            }
            float s = 0.f;
            #pragma unroll
            for (int a = 0; a < NACT; a++) { q[a] = expf(q[a] - m); s += q[a]; }
            float inv = 1.f / s;
            #pragma unroll
            for (int a = 0; a < NACT; a++)
                out[t * NACT + a] = q[a] * inv;
        }
    }
}

extern "C" void kernel_launch(void* const* d_in, const int* in_sizes, int n_in,
                              void* d_out, int out_size)
{
    const float* X  = (const float*)d_in[0];   // [64,2,64,64] (batch 0 only)
    const int*   S1 = (const int*)d_in[1];     // [64]
    const int*   S2 = (const int*)d_in[2];     // [64]
    const float* Wh = (const float*)d_in[3];   // [150,2,3,3]
    const float* bh = (const float*)d_in[4];   // [150]
    const float* Wr = (const float*)d_in[5];   // [1,150,1,1]
    const float* Wq = (const float*)d_in[6];   // [8,2,3,3]
    float* out = (float*)d_out;                // [64,8]

    vin_kernel<<<NCL, NTH>>>(X, S1, S2, Wh, bh, Wr, Wq, out);
}

// round 14
// speedup vs baseline: 1.0025x; 1.0025x over previous
#include <cuda_runtime.h>
#include <math.h>
#include <stdint.h>

// VIN full-grid 8-CTA cluster with 4-deep ghost zones + mbarrier group sync:
// each CTA owns 8 rows and computes a trapezoid band (14/12/10/8 rows over 4
// sub-sweeps) from purely local SMEM; ghosts are refreshed only every 4
// sweeps via st.shared::cluster + remote mbarrier.arrive (4 sync events for
// 19 sweeps instead of 19). 4 lanes per cell-pair / 2 actions per lane keeps
// the packed f32x2 weights register-resident (18 u64 = 36 regs). All index
// math is power-of-2. Only batch 0 reaches the output; the 150-ch hidden
// conv collapses into a 2-ch 3x3 effective conv; qr precomputed once.

#define NCL 8
#define RPC 8
#define GD 4
#define BROWS 16               // band rows rbase-4 .. rbase+11
#define PW 66
#define NTH 512
#define VSZ (BROWS * PW)       // 1056
#define XROWS 18               // X rows rbase-5 .. rbase+12
#define QSTR 900               // u64 per sub plane: 14*32*2 + 4 pad

// dynamic smem layout (bytes)
#define OFF_QR2  0
#define OFF_F    (4 * QSTR * 8)
#define F_XS     0                              // [2][18][66]
#define F_RP     (F_XS + 2 * XROWS * PW)        // [16][66]
#define F_V      (F_RP + VSZ)                   // vA, vB contiguous
#define F_WQS    (F_V + 2 * VSZ)
#define F_PART   (F_WQS + 144)
#define F_WEFF   (F_PART + 152)
#define F_TOTAL  (F_WEFF + 19)
#define SMEM_BYTES (OFF_F + F_TOTAL * 4)

__device__ __forceinline__ uint32_t s2u(const void* p) {
    return (uint32_t)__cvta_generic_to_shared(p);
}
__device__ __forceinline__ uint64_t pack2(float x, float y) {
    uint64_t r;
    asm("mov.b64 %0, {%1, %2};" : "=l"(r) : "f"(x), "f"(y));
    return r;
}
__device__ __forceinline__ float2 unpack2(uint64_t v) {
    float2 f;
    asm("mov.b64 {%0, %1}, %2;" : "=f"(f.x), "=f"(f.y) : "l"(v));
    return f;
}
__device__ __forceinline__ uint64_t fma2(uint64_t a, uint64_t b, uint64_t c) {
    uint64_t d;
    asm("fma.rn.f32x2 %0, %1, %2, %3;" : "=l"(d) : "l"(a), "l"(b), "l"(c));
    return d;
}
__device__ __forceinline__ void cluster_sync() {
    asm volatile("barrier.cluster.arrive.aligned;" ::: "memory");
    asm volatile("barrier.cluster.wait.aligned;" ::: "memory");
}
__device__ __forceinline__ void halo_out1(uint32_t laddr, uint32_t rank,
                                          float v, uint32_t lmbar) {
    asm volatile(
        "{\n\t.reg .b32 ra, rb;\n\t"
        "mapa.shared::cluster.u32 ra, %0, %1;\n\t"
        "st.shared::cluster.f32 [ra], %2;\n\t"
        "mapa.shared::cluster.u32 rb, %3, %1;\n\t"
        "mbarrier.arrive.release.cluster.shared::cluster.b64 _, [rb];\n\t}"
        :: "r"(laddr), "r"(rank), "f"(v), "r"(lmbar) : "memory");
}
__device__ __forceinline__ void mbar_wait(uint32_t addr, uint32_t parity) {
    asm volatile(
        "{\n\t.reg .pred P;\n\t"
        "W%=:\n\t"
        "mbarrier.try_wait.parity.acquire.cluster.shared::cta.b64 P, [%0], %1, 0x989680;\n\t"
        "@P bra D%=;\n\t"
        "bra W%=;\n\t"
        "D%=:\n\t}"
        :: "r"(addr), "r"(parity) : "memory");
}

// One sub-sweep: NR rows (ROW0 = 1+S), NPASS passes. rowk=(t>>7), p=(t>>2)&31.
#define SUBITER(NR, S, NPASS)                                                 \
{                                                                             \
    const float* cur = vb + parity * VSZ;                                     \
    float* nxt = vb + (parity ^ 1) * VSZ;                                     \
    _Pragma("unroll")                                                         \
    for (int k = 0; k < NPASS; k++) {                                         \
        const int row = rowk + 4 * k;                                         \
        const int br = row + 1 + (S);                                         \
        const bool wr = (row < (NR)) && (sub < 2) &&                          \
                        ((unsigned)(gbase + br) < 64u);                       \
        const int roff = (br - 1) * PW + 2 * p;                               \
        ulonglong2 qq = *(const ulonglong2*)(qr2s + ((br - 1) * 32 + p) * 2); \
        uint64_t a0 = qq.x, a1 = qq.y;                                        \
        _Pragma("unroll")                                                     \
        for (int ky = 0; ky < 3; ky++) {                                      \
            const uint64_t* rowp = (const uint64_t*)(cur + roff + ky * PW);   \
            uint64_t a01 = rowp[0], a23 = rowp[1];                            \
            float2 f01 = unpack2(a01), f23 = unpack2(a23);                    \
            uint64_t pm = pack2(f01.y, f23.x);                                \
            a0 = fma2(wpA[ky * 3 + 0], a01, a0);                              \
            a0 = fma2(wpA[ky * 3 + 1], pm,  a0);                              \
            a0 = fma2(wpA[ky * 3 + 2], a23, a0);                              \
            a1 = fma2(wpB[ky * 3 + 0], a01, a1);                              \
            a1 = fma2(wpB[ky * 3 + 1], pm,  a1);                              \
            a1 = fma2(wpB[ky * 3 + 2], a23, a1);                              \
        }                                                                     \
        float2 f0 = unpack2(a0), f1 = unpack2(a1);                            \
        float v0 = fmaxf(f0.x, f1.x);                                         \
        float v1 = fmaxf(f0.y, f1.y);                                         \
        v0 = fmaxf(v0, __shfl_xor_sync(0xffffffffu, v0, 1));                  \
        v1 = fmaxf(v1, __shfl_xor_sync(0xffffffffu, v1, 1));                  \
        v0 = fmaxf(v0, __shfl_xor_sync(0xffffffffu, v0, 2));                  \
        v1 = fmaxf(v1, __shfl_xor_sync(0xffffffffu, v1, 2));                  \
        if (wr) nxt[br * PW + 1 + 2 * p + sub] = (sub & 1) ? v1 : v0;         \
    }                                                                         \
    __syncthreads();                                                          \
    parity ^= 1;                                                              \
}

__global__ __launch_bounds__(NTH, 1) __cluster_dims__(NCL, 1, 1)
void vin_kernel(const float* __restrict__ X,
                const int* __restrict__ S1,
                const int* __restrict__ S2,
                const float* __restrict__ Wh,
                const float* __restrict__ bh,
                const float* __restrict__ Wr,
                const float* __restrict__ Wq,
                float* __restrict__ out)
{
    extern __shared__ char smem_raw[];
    uint64_t* qr2 = (uint64_t*)(smem_raw + OFF_QR2);    // [4][14][32][2] padded
    float* fb  = (float*)(smem_raw + OFF_F);
    float* Xs  = fb + F_XS;
    float* rp  = fb + F_RP;
    float* vb  = fb + F_V;                              // vA then vB
    float* wqs = fb + F_WQS;
    float* part = fb + F_PART;
    float* weff = fb + F_WEFF;
    __shared__ unsigned long long mbar;

    const int t = threadIdx.x;
    const int rank = blockIdx.x;
    const int rbase = rank * RPC;
    const int gbase = rbase - GD;           // global row of buffer row 0
    const int sub = t & 3;                  // lane-in-task: actions 2sub,2sub+1
    const int p = (t >> 2) & 31;            // pair: global cols 2p, 2p+1
    const int rowk = t >> 7;                // 0..3
    const uint64_t* qr2s = (const uint64_t*)qr2 + sub * QSTR;
    const uint32_t mb = s2u(&mbar);

    // ---- init: zero v/rp/qr2, stage Wq, collapse partials, mbar ----
    for (int i = t; i < 2 * VSZ; i += NTH) vb[i] = 0.f;
    for (int i = t; i < VSZ; i += NTH) rp[i] = 0.f;
    for (int i = t; i < 4 * QSTR; i += NTH) qr2[i] = 0ull;
    if (t < 144) wqs[t] = Wq[t];
    if (t < 152) {
        int pp = t >> 3, c = t & 7;
        float s = 0.f;
        for (int h = c; h < 150; h += 8)
            s += Wr[h] * (pp < 18 ? Wh[h * 18 + pp] : bh[h]);
        part[pp * 8 + c] = s;
    }
    if (t == 0) {
        int nb = (rank > 0) + (rank < NCL - 1);
        asm volatile("mbarrier.init.shared.b64 [%0], %1;"
                     :: "r"(mb), "r"(256 * nb) : "memory");
    }
    __syncthreads();
    if (t < 19) {
        float s = 0.f;
        #pragma unroll
        for (int c = 0; c < 8; c++) s += part[t * 8 + c];
        weff[t] = s;
    }
    // ---- load X band rows rbase-5..rbase+12, zero outside grid ----
    for (int idx = t; idx < 2 * XROWS * PW; idx += NTH) {
        int c = idx / (XROWS * PW);
        int rem = idx - c * (XROWS * PW);
        int xr = rem / PW;
        int xc = rem - xr * PW;
        int gy = rbase - 5 + xr, gx = xc - 1;
        float v = 0.f;
        if ((unsigned)gy < 64u && (unsigned)gx < 64u)
            v = X[c * 4096 + gy * 64 + gx];
        Xs[c * XROWS * PW + xr * PW + xc] = v;
    }
    __syncthreads();

    // ---- reward r over buffer rows 0..15 (in-grid only; else stays 0) ----
    {
        float we[18];
        #pragma unroll
        for (int q = 0; q < 18; q++) we[q] = weff[q];
        const float b0 = weff[18];
        #pragma unroll
        for (int k = 0; k < 2; k++) {
            int idx = t + k * NTH;
            int br = idx >> 6, j = idx & 63;
            int gy = gbase + br;
            if ((unsigned)gy >= 64u) continue;
            float acc = b0;
            #pragma unroll
            for (int c = 0; c < 2; c++)
                #pragma unroll
                for (int ky = 0; ky < 3; ky++)
                    #pragma unroll
                    for (int kx = 0; kx < 3; kx++)
                        acc = fmaf(we[c * 9 + ky * 3 + kx],
                                   Xs[c * XROWS * PW + (br + ky) * PW + j + kx],
                                   acc);
            rp[br * PW + j + 1] = acc;
        }
    }
    __syncthreads();

    // ---- qr = conv(r, Wq[:,0]) for buffer rows 1..14 (qr idx 0..13) ----
    {
        uint64_t wrA[9], wrB[9];
        #pragma unroll
        for (int q = 0; q < 9; q++) {
            float wa = wqs[(2 * sub) * 18 + q];
            float wb = wqs[(2 * sub + 1) * 18 + q];
            wrA[q] = pack2(wa, wa);
            wrB[q] = pack2(wb, wb);
        }
        #pragma unroll
        for (int k = 0; k < 4; k++) {
            int task = (t >> 2) + k * 128;         // 0..511; valid < 448
            int qrow = task >> 5;                  // 0..13 (qr idx)
            int pp = task & 31;
            int br = qrow + 1;
            bool act = (task < 448) && ((unsigned)(gbase + br) < 64u);
            uint64_t a0 = 0ull, a1 = 0ull;
            #pragma unroll
            for (int ky = 0; ky < 3; ky++) {
                const uint64_t* rowp =
                    (const uint64_t*)(rp + (br - 1 + ky) * PW + 2 * pp);
                uint64_t a01 = rowp[0], a23 = rowp[1];
                float2 f01 = unpack2(a01), f23 = unpack2(a23);
                uint64_t pm = pack2(f01.y, f23.x);
                a0 = fma2(wrA[ky * 3 + 0], a01, a0);
                a0 = fma2(wrA[ky * 3 + 1], pm,  a0);
                a0 = fma2(wrA[ky * 3 + 2], a23, a0);
                a1 = fma2(wrB[ky * 3 + 0], a01, a1);
                a1 = fma2(wrB[ky * 3 + 1], pm,  a1);
                a1 = fma2(wrB[ky * 3 + 2], a23, a1);
            }
            if (act) {
                ulonglong2 qq; qq.x = a0; qq.y = a1;
                *(ulonglong2*)((uint64_t*)qr2 + sub * QSTR + (qrow * 32 + pp) * 2) = qq;
            }
        }
    }
    // v-channel weights (18 u64 = 36 regs, register-resident)
    uint64_t wpA[9], wpB[9];
    #pragma unroll
    for (int q = 0; q < 9; q++) {
        float wa = wqs[(2 * sub) * 18 + 9 + q];
        float wb = wqs[(2 * sub + 1) * 18 + 9 + q];
        wpA[q] = pack2(wa, wa);
        wpB[q] = pack2(wb, wb);
    }
    __syncthreads();
    cluster_sync();   // mbar init + zeroed buffers visible cluster-wide

    // ---- 19 sweeps = 4 ghost-groups of 4 + final group of 3 ----
    int parity = 0;
    #pragma unroll 1
    for (int gi = 0; gi < 4; gi++) {
        if (gi > 0) mbar_wait(mb, (gi - 1) & 1);
        SUBITER(14, 0, 4);
        SUBITER(12, 1, 3);
        SUBITER(10, 2, 3);
        SUBITER(8, 3, 2);
        // exchange: parity back to 0, freshest own rows (4..11) live in vA
        {
            int rr = t >> 6;                 // 0..7 -> own buffer row 4+rr
            int j = t & 63;
            float v = vb[(4 + rr) * PW + 1 + j];
            if (rr < 4) {
                if (rank > 0)
                    halo_out1(s2u(vb + (12 + rr) * PW + 1 + j),
                              (uint32_t)(rank - 1), v, mb);
            } else {
                if (rank < NCL - 1)
                    halo_out1(s2u(vb + (rr - 4) * PW + 1 + j),
                              (uint32_t)(rank + 1), v, mb);
            }
        }
    }
    mbar_wait(mb, 1);                        // phase of exchange #4
    SUBITER(14, 0, 4);                       // sweep 17
    SUBITER(12, 1, 3);                       // sweep 18
    SUBITER(10, 2, 3);                       // sweep 19 -> rows [3,12] fresh
    // parity flipped 19 times -> v19 in vB

    // ---- q at the 64 query points from v19, softmax ----
    if (t < 64) {
        int qi = S1[t], qj = S2[t];
        if ((qi >> 3) == rank) {
            const float* cur = vb + VSZ;     // vB
            int lr = qi - rbase;             // 0..7; output buffer row lr+4
            float q[8];
            float m = -INFINITY;
            #pragma unroll
            for (int a = 0; a < 8; a++) {
                uint64_t qv = qr2[(a >> 1) * QSTR +
                                  ((lr + 3) * 32 + (qj >> 1)) * 2 + (a & 1)];
                float2 f = unpack2(qv);
                float acc = (qj & 1) ? f.y : f.x;
                #pragma unroll
                for (int ky = 0; ky < 3; ky++)
                    #pragma unroll
                    for (int kx = 0; kx < 3; kx++)
                        acc = fmaf(wqs[a * 18 + 9 + ky * 3 + kx],
                                   cur[(lr + 3 + ky) * PW + qj + kx], acc);
                q[a] = acc;
                m = fmaxf(m, acc);
            }
            float s = 0.f;
            #pragma unroll
            for (int a = 0; a < 8; a++) { q[a] = expf(q[a] - m); s += q[a]; }
            float inv = 1.f / s;
            #pragma unroll
            for (int a = 0; a < 8; a++)
                out[t * 8 + a] = q[a] * inv;
        }
    }
}

extern "C" void kernel_launch(void* const* d_in, const int* in_sizes, int n_in,
                              void* d_out, int out_size)
{
    const float* X  = (const float*)d_in[0];   // [64,2,64,64] (batch 0 only)
    const int*   S1 = (const int*)d_in[1];     // [64]
    const int*   S2 = (const int*)d_in[2];     // [64]
    const float* Wh = (const float*)d_in[3];   // [150,2,3,3]
    const float* bh = (const float*)d_in[4];   // [150]
    const float* Wr = (const float*)d_in[5];   // [1,150,1,1]
    const float* Wq = (const float*)d_in[6];   // [8,2,3,3]
    float* out = (float*)d_out;                // [64,8]

    cudaFuncSetAttribute(vin_kernel,
                         cudaFuncAttributeMaxDynamicSharedMemorySize,
                         SMEM_BYTES);
    vin_kernel<<<NCL, NTH, SMEM_BYTES>>>(X, S1, S2, Wh, bh, Wr, Wq, out);
}